// round 13
// baseline (speedup 1.0000x reference)
#include <cuda_runtime.h>
#include <cuda_fp16.h>

#define NMAX 50000
#define EMAX 800000
#define HC   128
#define FIN  64
#define NGEMMB 444

// ---------------- scratch (static device arrays; no allocation) ----------------
__device__ float h_g[NMAX * HC];        // x @ W                [N,128]
__device__ float res_g[NMAX * HC];      // x @ res_w + res_b    [N,128]
__device__ float a_src_g[NMAX * 4];     // per-head src coeff   [N,4]
__device__ float a_dst_g[NMAX * 4];     // per-head dst coeff   [N,4]
__device__ int   deg_g[NMAX];           // zero at load; scan re-zeros after use
__device__ int   rowptr_g[NMAX + 1];
__device__ int   rowcur_g[NMAX];
__device__ int   col_g[EMAX];
__device__ int   src_g[EMAX];
__device__ int   dst_g[EMAX];

#define LEAKY(v) ((v) >= 0.f ? (v) : 0.2f * (v))

__device__ __forceinline__ void mma16816(float* c, const unsigned* a, const unsigned* b)
{
    asm volatile(
        "mma.sync.aligned.m16n8k16.row.col.f32.f16.f16.f32 "
        "{%0,%1,%2,%3}, {%4,%5,%6,%7}, {%8,%9}, {%0,%1,%2,%3};"
        : "+f"(c[0]), "+f"(c[1]), "+f"(c[2]), "+f"(c[3])
        : "r"(a[0]), "r"(a[1]), "r"(a[2]), "r"(a[3]), "r"(b[0]), "r"(b[1]));
}

#define W_WORDS (256 * 36)
#define X_WORDS (32 * 36)

// ---------------- fused phase-1 kernel ----------------
// blocks [0, NGEMMB): tensor-core GEMM (h, res, att dots)
// blocks [NGEMMB, ...): extract src/dst + degree histogram (dtype detect folded)
__global__ void phase1_kernel(const float* __restrict__ x, const float* __restrict__ W,
                              const float* __restrict__ Rw, const float* __restrict__ Rb,
                              const float* __restrict__ att_s, const float* __restrict__ att_d,
                              const void* __restrict__ raw,
                              int n, int ntiles, int E)
{
    extern __shared__ unsigned smw[];
    int t = threadIdx.x;

    if (blockIdx.x >= NGEMMB) {
        // ---- extract + hist part ----
        __shared__ int s_has_nonzero_odd;
        const int* p32 = (const int*)raw;
        if (t == 0) s_has_nonzero_odd = 0;
        __syncthreads();
        int nwords = 1024;
        if (nwords > 2 * E) nwords = 2 * E;
        int nz = 0;
        for (int j = t; j < nwords / 2; j += blockDim.x)
            nz |= p32[2 * j + 1];
        if (nz) atomicOr(&s_has_nonzero_odd, 1);
        __syncthreads();
        int is64 = !s_has_nonzero_odd;

        int i = (blockIdx.x - NGEMMB) * blockDim.x + t;
        if (i >= E) return;
        int s, d;
        if (is64) {
            const long long* p = (const long long*)raw;
            s = (int)p[i];
            d = (int)p[E + i];
        } else {
            s = p32[i];
            d = p32[E + i];
        }
        src_g[i] = s;
        dst_g[i] = d;
        atomicAdd(&deg_g[d], 1);
        return;
    }

    // ---- tensor-core GEMM part ----
    unsigned* Wsh = smw;                       // fp16 n-major [col][k], stride 36 words
    unsigned* xsh = smw + W_WORDS;             // fp16 [node][k], stride 36 words
    float* asl = (float*)(smw + W_WORDS + X_WORDS);
    float* adl = asl + 128;
    float* rbs = adl + 128;

    for (int idx = t; idx < FIN * 256; idx += 256) {
        int k = idx >> 8, c = idx & 255;
        float v = (c < 128) ? W[k * 128 + c] : Rw[k * 128 + (c - 128)];
        ((__half*)Wsh)[c * 72 + k] = __float2half(v);
    }
    if (t < 128) { asl[t] = att_s[t]; adl[t] = att_d[t]; rbs[t] = Rb[t]; }
    __syncthreads();

    int lane = t & 31, wid = t >> 5;
    int g = lane >> 2, qi = lane & 3;
    bool is_h = wid < 4;
    int colhalf = (wid & 3) * 32;

    for (int tile = blockIdx.x; tile < ntiles; tile += NGEMMB) {
        int nb = tile << 5;
        {
            int r = t >> 3, k0 = (t & 7) * 8;
            int node = nb + r;
            if (node >= n) node = n - 1;
            const float4* xr = (const float4*)(x + (size_t)node * FIN + k0);
            float4 v0 = xr[0], v1 = xr[1];
            __half2* dst = (__half2*)((__half*)xsh + r * 72 + k0);
            dst[0] = __floats2half2_rn(v0.x, v0.y);
            dst[1] = __floats2half2_rn(v0.z, v0.w);
            dst[2] = __floats2half2_rn(v1.x, v1.y);
            dst[3] = __floats2half2_rn(v1.z, v1.w);
        }
        __syncthreads();

        float acc[2][4][4];
#pragma unroll
        for (int nf = 0; nf < 2; nf++)
#pragma unroll
            for (int cf = 0; cf < 4; cf++)
#pragma unroll
                for (int q = 0; q < 4; q++) acc[nf][cf][q] = 0.f;

#pragma unroll
        for (int ks = 0; ks < 4; ks++) {
            int kw = ks * 8;
            unsigned a[2][4], b[4][2];
#pragma unroll
            for (int nf = 0; nf < 2; nf++) {
                unsigned base = (unsigned)(nf * 16 + g) * 36 + kw + qi;
                a[nf][0] = xsh[base];
                a[nf][1] = xsh[base + 8 * 36];
                a[nf][2] = xsh[base + 4];
                a[nf][3] = xsh[base + 4 + 8 * 36];
            }
#pragma unroll
            for (int cf = 0; cf < 4; cf++) {
                unsigned base = (unsigned)(wid * 32 + cf * 8 + g) * 36 + kw + qi;
                b[cf][0] = Wsh[base];
                b[cf][1] = Wsh[base + 4];
            }
#pragma unroll
            for (int nf = 0; nf < 2; nf++)
#pragma unroll
                for (int cf = 0; cf < 4; cf++)
                    mma16816(acc[nf][cf], a[nf], b[cf]);
        }
        __syncthreads();

        float* outb = is_h ? h_g : res_g;
#pragma unroll
        for (int nf = 0; nf < 2; nf++) {
            int node0 = nb + nf * 16 + g;
            int node1 = node0 + 8;
            float s0 = 0.f, d0 = 0.f, s1 = 0.f, d1 = 0.f;
#pragma unroll
            for (int cf = 0; cf < 4; cf++) {
                int c = colhalf + cf * 8 + qi * 2;
                float add0 = is_h ? 0.f : rbs[c];
                float add1 = is_h ? 0.f : rbs[c + 1];
                if (node0 < n) {
                    float2 v = make_float2(acc[nf][cf][0] + add0, acc[nf][cf][1] + add1);
                    *(float2*)&outb[(size_t)node0 * HC + c] = v;
                }
                if (node1 < n) {
                    float2 v = make_float2(acc[nf][cf][2] + add0, acc[nf][cf][3] + add1);
                    *(float2*)&outb[(size_t)node1 * HC + c] = v;
                }
                if (is_h) {
                    float as0 = asl[c], as1 = asl[c + 1];
                    float ad0 = adl[c], ad1 = adl[c + 1];
                    s0 += acc[nf][cf][0] * as0 + acc[nf][cf][1] * as1;
                    d0 += acc[nf][cf][0] * ad0 + acc[nf][cf][1] * ad1;
                    s1 += acc[nf][cf][2] * as0 + acc[nf][cf][3] * as1;
                    d1 += acc[nf][cf][2] * ad0 + acc[nf][cf][3] * ad1;
                }
            }
            if (is_h) {
#pragma unroll
                for (int off = 1; off < 4; off <<= 1) {
                    s0 += __shfl_xor_sync(0xffffffffu, s0, off);
                    d0 += __shfl_xor_sync(0xffffffffu, d0, off);
                    s1 += __shfl_xor_sync(0xffffffffu, s1, off);
                    d1 += __shfl_xor_sync(0xffffffffu, d1, off);
                }
                if (qi == 0) {
                    if (node0 < n) { a_src_g[node0 * 4 + wid] = s0; a_dst_g[node0 * 4 + wid] = d0; }
                    if (node1 < n) { a_src_g[node1 * 4 + wid] = s1; a_dst_g[node1 * 4 + wid] = d1; }
                }
            }
        }
    }
}

// ---------------- single-block scan over N (re-zeros deg for next launch) -----
__global__ void scan_kernel(int n)
{
    __shared__ int sh[1024];
    int t = threadIdx.x;
    int chunk = (n + 1023) >> 10;
    int s0 = t * chunk;
    int s1 = s0 + chunk;
    if (s0 > n) s0 = n;
    if (s1 > n) s1 = n;
    int s = 0;
#pragma unroll 4
    for (int i = s0; i < s1; i++) s += deg_g[i];
    sh[t] = s;
    __syncthreads();
#pragma unroll
    for (int off = 1; off < 1024; off <<= 1) {
        int v = (t >= off) ? sh[t - off] : 0;
        __syncthreads();
        sh[t] += v;
        __syncthreads();
    }
    int run = sh[t] - s;  // exclusive prefix
    for (int i = s0; i < s1; i++) {
        int d = deg_g[i];
        rowptr_g[i] = run;
        rowcur_g[i] = run;
        deg_g[i] = 0;       // leave zeroed for the next launch (graph replay)
        run += d;
    }
    if (t == 1023) rowptr_g[n] = sh[1023];
}

// ---------------- scatter (2 edges/thread, guarded) ----------------
__global__ void scatter_kernel(int E, int T)
{
    int t = blockIdx.x * blockDim.x + threadIdx.x;
    if (t >= T) return;
    int i0 = t, i1 = t + T;
    int d0, s0, d1, s1;
    d0 = dst_g[i0]; s0 = src_g[i0];
    if (i1 < E) { d1 = dst_g[i1]; s1 = src_g[i1]; }
    int p0 = atomicAdd(&rowcur_g[d0], 1);
    int p1;
    if (i1 < E) p1 = atomicAdd(&rowcur_g[d1], 1);
    col_g[p0] = s0;
    if (i1 < E) col_g[p1] = s1;
}

// ---------------- fused aggregate + softmax + ELU + residual + LayerNorm ------
// One warp per destination node. Lane l holds channels [4l,4l+4), head = l/8.
__global__ void aggregate_kernel(const float* __restrict__ bias,
                                 const float* __restrict__ lng, const float* __restrict__ lnb,
                                 float* __restrict__ out, int n)
{
    int warp = (blockIdx.x * blockDim.x + threadIdx.x) >> 5;
    int lane = threadIdx.x & 31;
    if (warp >= n) return;
    int v = warp;
    int head = lane >> 3;

    float adh = a_dst_g[v * 4 + head];
    const float4* hp = (const float4*)h_g;

    // self loop
    float w0 = __expf(LEAKY(a_src_g[v * 4 + head] + adh));
    float4 hv = hp[v * 32 + lane];
    float4 acc = make_float4(w0 * hv.x, w0 * hv.y, w0 * hv.z, w0 * hv.w);
    float dsum = w0;

    int rs = rowptr_g[v], re = rowptr_g[v + 1];
    int i = rs;
    for (; i + 4 <= re; i += 4) {
        int u0 = col_g[i], u1 = col_g[i + 1], u2 = col_g[i + 2], u3 = col_g[i + 3];
        float e0 = a_src_g[u0 * 4 + head];
        float e1 = a_src_g[u1 * 4 + head];
        float e2 = a_src_g[u2 * 4 + head];
        float e3 = a_src_g[u3 * 4 + head];
        float4 h0 = hp[u0 * 32 + lane];
        float4 h1 = hp[u1 * 32 + lane];
        float4 h2 = hp[u2 * 32 + lane];
        float4 h3 = hp[u3 * 32 + lane];
        float x0 = __expf(LEAKY(e0 + adh));
        float x1 = __expf(LEAKY(e1 + adh));
        float x2 = __expf(LEAKY(e2 + adh));
        float x3 = __expf(LEAKY(e3 + adh));
        acc.x += x0 * h0.x + x1 * h1.x + x2 * h2.x + x3 * h3.x;
        acc.y += x0 * h0.y + x1 * h1.y + x2 * h2.y + x3 * h3.y;
        acc.z += x0 * h0.z + x1 * h1.z + x2 * h2.z + x3 * h3.z;
        acc.w += x0 * h0.w + x1 * h1.w + x2 * h2.w + x3 * h3.w;
        dsum += x0 + x1 + x2 + x3;
    }
    for (; i < re; i++) {
        int u = col_g[i];
        float wv = __expf(LEAKY(a_src_g[u * 4 + head] + adh));
        float4 hu = hp[u * 32 + lane];
        acc.x += wv * hu.x;
        acc.y += wv * hu.y;
        acc.z += wv * hu.z;
        acc.w += wv * hu.w;
        dsum += wv;
    }

    float inv = 1.f / dsum;
    float4 b = ((const float4*)bias)[lane];
    float4 o;
    o.x = acc.x * inv + b.x;
    o.y = acc.y * inv + b.y;
    o.z = acc.z * inv + b.z;
    o.w = acc.w * inv + b.w;

    // ELU
    o.x = o.x > 0.f ? o.x : expm1f(o.x);
    o.y = o.y > 0.f ? o.y : expm1f(o.y);
    o.z = o.z > 0.f ? o.z : expm1f(o.z);
    o.w = o.w > 0.f ? o.w : expm1f(o.w);

    // residual
    float4 r = ((const float4*)res_g)[v * 32 + lane];
    o.x += r.x; o.y += r.y; o.z += r.z; o.w += r.w;

    // LayerNorm over 128 (warp-wide)
    float s = o.x + o.y + o.z + o.w;
#pragma unroll
    for (int off = 16; off; off >>= 1) s += __shfl_xor_sync(0xffffffffu, s, off);
    float mean = s * (1.f / 128.f);

    float cx = o.x - mean, cy = o.y - mean, cz = o.z - mean, cw = o.w - mean;
    float sq = cx * cx + cy * cy + cz * cz + cw * cw;
#pragma unroll
    for (int off = 16; off; off >>= 1) sq += __shfl_xor_sync(0xffffffffu, sq, off);
    float rinv = rsqrtf(sq * (1.f / 128.f) + 1e-5f);

    float4 g  = ((const float4*)lng)[lane];
    float4 lb = ((const float4*)lnb)[lane];
    float4 oo;
    oo.x = cx * rinv * g.x + lb.x;
    oo.y = cy * rinv * g.y + lb.y;
    oo.z = cz * rinv * g.z + lb.z;
    oo.w = cw * rinv * g.w + lb.w;

    ((float4*)out)[v * 32 + lane] = oo;
}

// ---------------- launch (single stream; aggregate = 4th submission) ----------
extern "C" void kernel_launch(void* const* d_in, const int* in_sizes, int n_in,
                              void* d_out, int out_size)
{
    const float* x     = (const float*)d_in[0];
    const void*  ei    = d_in[1];
    const float* W     = (const float*)d_in[2];
    const float* att_s = (const float*)d_in[3];
    const float* att_d = (const float*)d_in[4];
    const float* bias  = (const float*)d_in[5];
    const float* Rw    = (const float*)d_in[6];
    const float* Rb    = (const float*)d_in[7];
    const float* lng   = (const float*)d_in[8];
    const float* lnb   = (const float*)d_in[9];

    int n = in_sizes[0] / FIN;
    int E = in_sizes[1] / 2;
    int ntiles = (n + 31) / 32;
    int nExtract = (E + 255) / 256;
    int T = (E + 1) / 2;

    static int inited = 0;
    int p1_smem = (W_WORDS + X_WORDS + 384) * (int)sizeof(unsigned);  // ~43KB
    if (!inited) {
        cudaFuncSetAttribute(phase1_kernel, cudaFuncAttributeMaxDynamicSharedMemorySize, p1_smem);
        inited = 1;
    }

    phase1_kernel<<<NGEMMB + nExtract, 256, p1_smem>>>(x, W, Rw, Rb, att_s, att_d,
                                                       ei, n, ntiles, E);          // submission 1
    scan_kernel<<<1, 1024>>>(n);                                                   // submission 2
    scatter_kernel<<<((T + 255) / 256), 256>>>(E, T);                              // submission 3
    aggregate_kernel<<<(n + 7) / 8, 256>>>(bias, lng, lnb, (float*)d_out, n);      // submission 4 (profiled)
}

// round 14
// speedup vs baseline: 2.0034x; 2.0034x over previous
#include <cuda_runtime.h>
#include <cuda_fp16.h>

#define NMAX 50000
#define EMAX 800000
#define HC   128
#define FIN  64
#define SCAN_BS 512
#define SCAN_NB ((NMAX + SCAN_BS - 1) / SCAN_BS)   // 98

// ---------------- scratch (static device arrays; no allocation) ----------------
__device__ float h_g[NMAX * HC];        // x @ W                [N,128]
__device__ float res_g[NMAX * HC];      // x @ res_w + res_b    [N,128]
__device__ float a_src_g[NMAX * 4];     // per-head src coeff   [N,4]
__device__ float a_dst_g[NMAX * 4];     // per-head dst coeff   [N,4]
__device__ int   deg_g[NMAX];           // zero at load; scanC re-zeros after use
__device__ int   rowptr_g[NMAX + 1];
__device__ int   rowcur_g[NMAX];
__device__ int   col_g[EMAX];
__device__ int   src_g[EMAX];
__device__ int   dst_g[EMAX];
__device__ int   bsum_g[SCAN_NB + 1];
__device__ int   boff_g[SCAN_NB + 1];

#define LEAKY(v) ((v) >= 0.f ? (v) : 0.2f * (v))

// ---------------- extract src/dst + histogram (detection folded in) -----------
__global__ void extract_hist_kernel(const void* __restrict__ raw, int E)
{
    __shared__ int s_has_nonzero_odd;
    const int* p32 = (const int*)raw;

    if (threadIdx.x == 0) s_has_nonzero_odd = 0;
    __syncthreads();
    int nwords = 1024;
    if (nwords > 2 * E) nwords = 2 * E;
    int nz = 0;
    for (int j = threadIdx.x; j < nwords / 2; j += blockDim.x)
        nz |= p32[2 * j + 1];
    if (nz) atomicOr(&s_has_nonzero_odd, 1);
    __syncthreads();
    int is64 = !s_has_nonzero_odd;

    int i = blockIdx.x * blockDim.x + threadIdx.x;
    if (i >= E) return;
    int s, d;
    if (is64) {
        const long long* p = (const long long*)raw;
        s = (int)p[i];
        d = (int)p[E + i];
    } else {
        s = p32[i];
        d = p32[E + i];
    }
    src_g[i] = s;
    dst_g[i] = d;
    atomicAdd(&deg_g[d], 1);
}

// ---------------- parallel 3-phase scan ----------------
// A: per-block sums (coalesced)
__global__ void scanA_kernel(int n)
{
    __shared__ int sh[SCAN_BS];
    int t = threadIdx.x;
    int i = blockIdx.x * SCAN_BS + t;
    sh[t] = (i < n) ? deg_g[i] : 0;
    __syncthreads();
#pragma unroll
    for (int off = SCAN_BS / 2; off; off >>= 1) {
        if (t < off) sh[t] += sh[t + off];
        __syncthreads();
    }
    if (t == 0) bsum_g[blockIdx.x] = sh[0];
}

// B: exclusive scan of the block sums (1 small block)
__global__ void scanB_kernel(int n, int nb)
{
    __shared__ int sh[128];
    int t = threadIdx.x;   // blockDim = 128 >= nb
    int v = (t < nb) ? bsum_g[t] : 0;
    sh[t] = v;
    __syncthreads();
#pragma unroll
    for (int off = 1; off < 128; off <<= 1) {
        int u = (t >= off) ? sh[t - off] : 0;
        __syncthreads();
        sh[t] += u;
        __syncthreads();
    }
    if (t < nb) boff_g[t] = sh[t] - v;        // exclusive
    if (t == nb - 1) rowptr_g[n] = sh[t];     // total
}

// C: block-local exclusive scan + offset; writes rowptr/rowcur; re-zeros deg
__global__ void scanC_kernel(int n)
{
    __shared__ int sh[SCAN_BS];
    int t = threadIdx.x;
    int i = blockIdx.x * SCAN_BS + t;
    int v = (i < n) ? deg_g[i] : 0;
    sh[t] = v;
    __syncthreads();
#pragma unroll
    for (int off = 1; off < SCAN_BS; off <<= 1) {
        int u = (t >= off) ? sh[t - off] : 0;
        __syncthreads();
        sh[t] += u;
        __syncthreads();
    }
    if (i < n) {
        int r = boff_g[blockIdx.x] + sh[t] - v;   // exclusive prefix
        rowptr_g[i] = r;
        rowcur_g[i] = r;
        deg_g[i] = 0;                              // ready for next launch
    }
}

// ---------------- scatter (2 edges/thread, guarded) ----------------
__global__ void scatter_kernel(int E, int T)
{
    int t = blockIdx.x * blockDim.x + threadIdx.x;
    if (t >= T) return;
    int i0 = t, i1 = t + T;
    int d0 = dst_g[i0], s0 = src_g[i0];
    int d1, s1;
    if (i1 < E) { d1 = dst_g[i1]; s1 = src_g[i1]; }
    int p0 = atomicAdd(&rowcur_g[d0], 1);
    int p1;
    if (i1 < E) p1 = atomicAdd(&rowcur_g[d1], 1);
    col_g[p0] = s0;
    if (i1 < E) col_g[p1] = s1;
}

// ---------------- tensor-core GEMM: h = x@W ; res = x@res_w + b ; att dots ----
__device__ __forceinline__ void mma16816(float* c, const unsigned* a, const unsigned* b)
{
    asm volatile(
        "mma.sync.aligned.m16n8k16.row.col.f32.f16.f16.f32 "
        "{%0,%1,%2,%3}, {%4,%5,%6,%7}, {%8,%9}, {%0,%1,%2,%3};"
        : "+f"(c[0]), "+f"(c[1]), "+f"(c[2]), "+f"(c[3])
        : "r"(a[0]), "r"(a[1]), "r"(a[2]), "r"(a[3]), "r"(b[0]), "r"(b[1]));
}

#define W_WORDS (256 * 36)
#define X_WORDS (32 * 36)

__global__ void gemm_kernel(const float* __restrict__ x, const float* __restrict__ W,
                            const float* __restrict__ Rw, const float* __restrict__ Rb,
                            const float* __restrict__ att_s, const float* __restrict__ att_d,
                            int n, int ntiles)
{
    extern __shared__ unsigned smw[];
    unsigned* Wsh = smw;                       // fp16 n-major [col][k], stride 36 words
    unsigned* xsh = smw + W_WORDS;             // fp16 [node][k], stride 36 words
    float* asl = (float*)(smw + W_WORDS + X_WORDS);
    float* adl = asl + 128;
    float* rbs = adl + 128;

    int t = threadIdx.x;
    for (int idx = t; idx < FIN * 256; idx += 256) {
        int k = idx >> 8, c = idx & 255;
        float v = (c < 128) ? W[k * 128 + c] : Rw[k * 128 + (c - 128)];
        ((__half*)Wsh)[c * 72 + k] = __float2half(v);
    }
    if (t < 128) { asl[t] = att_s[t]; adl[t] = att_d[t]; rbs[t] = Rb[t]; }
    __syncthreads();

    int lane = t & 31, wid = t >> 5;
    int g = lane >> 2, qi = lane & 3;
    bool is_h = wid < 4;
    int colhalf = (wid & 3) * 32;

    for (int tile = blockIdx.x; tile < ntiles; tile += gridDim.x) {
        int nb = tile << 5;
        {
            int r = t >> 3, k0 = (t & 7) * 8;
            int node = nb + r;
            if (node >= n) node = n - 1;
            const float4* xr = (const float4*)(x + (size_t)node * FIN + k0);
            float4 v0 = xr[0], v1 = xr[1];
            __half2* dst = (__half2*)((__half*)xsh + r * 72 + k0);
            dst[0] = __floats2half2_rn(v0.x, v0.y);
            dst[1] = __floats2half2_rn(v0.z, v0.w);
            dst[2] = __floats2half2_rn(v1.x, v1.y);
            dst[3] = __floats2half2_rn(v1.z, v1.w);
        }
        __syncthreads();

        float acc[2][4][4];
#pragma unroll
        for (int nf = 0; nf < 2; nf++)
#pragma unroll
            for (int cf = 0; cf < 4; cf++)
#pragma unroll
                for (int q = 0; q < 4; q++) acc[nf][cf][q] = 0.f;

#pragma unroll
        for (int ks = 0; ks < 4; ks++) {
            int kw = ks * 8;
            unsigned a[2][4], b[4][2];
#pragma unroll
            for (int nf = 0; nf < 2; nf++) {
                unsigned base = (unsigned)(nf * 16 + g) * 36 + kw + qi;
                a[nf][0] = xsh[base];
                a[nf][1] = xsh[base + 8 * 36];
                a[nf][2] = xsh[base + 4];
                a[nf][3] = xsh[base + 4 + 8 * 36];
            }
#pragma unroll
            for (int cf = 0; cf < 4; cf++) {
                unsigned base = (unsigned)(wid * 32 + cf * 8 + g) * 36 + kw + qi;
                b[cf][0] = Wsh[base];
                b[cf][1] = Wsh[base + 4];
            }
#pragma unroll
            for (int nf = 0; nf < 2; nf++)
#pragma unroll
                for (int cf = 0; cf < 4; cf++)
                    mma16816(acc[nf][cf], a[nf], b[cf]);
        }
        __syncthreads();

        float* outb = is_h ? h_g : res_g;
#pragma unroll
        for (int nf = 0; nf < 2; nf++) {
            int node0 = nb + nf * 16 + g;
            int node1 = node0 + 8;
            float s0 = 0.f, d0 = 0.f, s1 = 0.f, d1 = 0.f;
#pragma unroll
            for (int cf = 0; cf < 4; cf++) {
                int c = colhalf + cf * 8 + qi * 2;
                float add0 = is_h ? 0.f : rbs[c];
                float add1 = is_h ? 0.f : rbs[c + 1];
                if (node0 < n) {
                    float2 v = make_float2(acc[nf][cf][0] + add0, acc[nf][cf][1] + add1);
                    *(float2*)&outb[(size_t)node0 * HC + c] = v;
                }
                if (node1 < n) {
                    float2 v = make_float2(acc[nf][cf][2] + add0, acc[nf][cf][3] + add1);
                    *(float2*)&outb[(size_t)node1 * HC + c] = v;
                }
                if (is_h) {
                    float as0 = asl[c], as1 = asl[c + 1];
                    float ad0 = adl[c], ad1 = adl[c + 1];
                    s0 += acc[nf][cf][0] * as0 + acc[nf][cf][1] * as1;
                    d0 += acc[nf][cf][0] * ad0 + acc[nf][cf][1] * ad1;
                    s1 += acc[nf][cf][2] * as0 + acc[nf][cf][3] * as1;
                    d1 += acc[nf][cf][2] * ad0 + acc[nf][cf][3] * ad1;
                }
            }
            if (is_h) {
#pragma unroll
                for (int off = 1; off < 4; off <<= 1) {
                    s0 += __shfl_xor_sync(0xffffffffu, s0, off);
                    d0 += __shfl_xor_sync(0xffffffffu, d0, off);
                    s1 += __shfl_xor_sync(0xffffffffu, s1, off);
                    d1 += __shfl_xor_sync(0xffffffffu, d1, off);
                }
                if (qi == 0) {
                    if (node0 < n) { a_src_g[node0 * 4 + wid] = s0; a_dst_g[node0 * 4 + wid] = d0; }
                    if (node1 < n) { a_src_g[node1 * 4 + wid] = s1; a_dst_g[node1 * 4 + wid] = d1; }
                }
            }
        }
    }
}

// ---------------- fused aggregate + softmax + ELU + residual + LayerNorm ------
__global__ void aggregate_kernel(const float* __restrict__ bias,
                                 const float* __restrict__ lng, const float* __restrict__ lnb,
                                 float* __restrict__ out, int n)
{
    int warp = (blockIdx.x * blockDim.x + threadIdx.x) >> 5;
    int lane = threadIdx.x & 31;
    if (warp >= n) return;
    int v = warp;
    int head = lane >> 3;

    float adh = a_dst_g[v * 4 + head];
    const float4* hp = (const float4*)h_g;

    // self loop
    float w0 = __expf(LEAKY(a_src_g[v * 4 + head] + adh));
    float4 hv = hp[v * 32 + lane];
    float4 acc = make_float4(w0 * hv.x, w0 * hv.y, w0 * hv.z, w0 * hv.w);
    float dsum = w0;

    int rs = rowptr_g[v], re = rowptr_g[v + 1];
    int i = rs;
    for (; i + 4 <= re; i += 4) {
        int u0 = col_g[i], u1 = col_g[i + 1], u2 = col_g[i + 2], u3 = col_g[i + 3];
        float e0 = a_src_g[u0 * 4 + head];
        float e1 = a_src_g[u1 * 4 + head];
        float e2 = a_src_g[u2 * 4 + head];
        float e3 = a_src_g[u3 * 4 + head];
        float4 h0 = hp[u0 * 32 + lane];
        float4 h1 = hp[u1 * 32 + lane];
        float4 h2 = hp[u2 * 32 + lane];
        float4 h3 = hp[u3 * 32 + lane];
        float x0 = __expf(LEAKY(e0 + adh));
        float x1 = __expf(LEAKY(e1 + adh));
        float x2 = __expf(LEAKY(e2 + adh));
        float x3 = __expf(LEAKY(e3 + adh));
        acc.x += x0 * h0.x + x1 * h1.x + x2 * h2.x + x3 * h3.x;
        acc.y += x0 * h0.y + x1 * h1.y + x2 * h2.y + x3 * h3.y;
        acc.z += x0 * h0.z + x1 * h1.z + x2 * h2.z + x3 * h3.z;
        acc.w += x0 * h0.w + x1 * h1.w + x2 * h2.w + x3 * h3.w;
        dsum += x0 + x1 + x2 + x3;
    }
    for (; i < re; i++) {
        int u = col_g[i];
        float wv = __expf(LEAKY(a_src_g[u * 4 + head] + adh));
        float4 hu = hp[u * 32 + lane];
        acc.x += wv * hu.x;
        acc.y += wv * hu.y;
        acc.z += wv * hu.z;
        acc.w += wv * hu.w;
        dsum += wv;
    }

    float inv = 1.f / dsum;
    float4 b = ((const float4*)bias)[lane];
    float4 o;
    o.x = acc.x * inv + b.x;
    o.y = acc.y * inv + b.y;
    o.z = acc.z * inv + b.z;
    o.w = acc.w * inv + b.w;

    // ELU
    o.x = o.x > 0.f ? o.x : expm1f(o.x);
    o.y = o.y > 0.f ? o.y : expm1f(o.y);
    o.z = o.z > 0.f ? o.z : expm1f(o.z);
    o.w = o.w > 0.f ? o.w : expm1f(o.w);

    // residual
    float4 r = ((const float4*)res_g)[v * 32 + lane];
    o.x += r.x; o.y += r.y; o.z += r.z; o.w += r.w;

    // LayerNorm over 128 (warp-wide)
    float s = o.x + o.y + o.z + o.w;
#pragma unroll
    for (int off = 16; off; off >>= 1) s += __shfl_xor_sync(0xffffffffu, s, off);
    float mean = s * (1.f / 128.f);

    float cx = o.x - mean, cy = o.y - mean, cz = o.z - mean, cw = o.w - mean;
    float sq = cx * cx + cy * cy + cz * cz + cw * cw;
#pragma unroll
    for (int off = 16; off; off >>= 1) sq += __shfl_xor_sync(0xffffffffu, sq, off);
    float rinv = rsqrtf(sq * (1.f / 128.f) + 1e-5f);

    float4 g  = ((const float4*)lng)[lane];
    float4 lb = ((const float4*)lnb)[lane];
    float4 oo;
    oo.x = cx * rinv * g.x + lb.x;
    oo.y = cy * rinv * g.y + lb.y;
    oo.z = cz * rinv * g.z + lb.z;
    oo.w = cw * rinv * g.w + lb.w;

    ((float4*)out)[v * 32 + lane] = oo;
}

// ---------------- launch (fork-join: CSR build overlaps GEMM) ----------------
extern "C" void kernel_launch(void* const* d_in, const int* in_sizes, int n_in,
                              void* d_out, int out_size)
{
    const float* x     = (const float*)d_in[0];
    const void*  ei    = d_in[1];
    const float* W     = (const float*)d_in[2];
    const float* att_s = (const float*)d_in[3];
    const float* att_d = (const float*)d_in[4];
    const float* bias  = (const float*)d_in[5];
    const float* Rw    = (const float*)d_in[6];
    const float* Rb    = (const float*)d_in[7];
    const float* lng   = (const float*)d_in[8];
    const float* lnb   = (const float*)d_in[9];

    int n = in_sizes[0] / FIN;
    int E = in_sizes[1] / 2;
    int ntiles = (n + 31) / 32;
    int nb = (n + SCAN_BS - 1) / SCAN_BS;
    int T = (E + 1) / 2;

    static cudaStream_t s2 = 0;
    static cudaEvent_t evFork = 0, evJoin = 0;
    static int inited = 0;
    int gemm_smem = (W_WORDS + X_WORDS + 384) * (int)sizeof(unsigned);  // ~43KB
    if (!inited) {
        cudaFuncSetAttribute(gemm_kernel, cudaFuncAttributeMaxDynamicSharedMemorySize, gemm_smem);
        cudaStreamCreateWithFlags(&s2, cudaStreamNonBlocking);
        cudaEventCreateWithFlags(&evFork, cudaEventDisableTiming);
        cudaEventCreateWithFlags(&evJoin, cudaEventDisableTiming);
        inited = 1;
    }

    // fork: s2 does the CSR build while stream 0 does the GEMM
    cudaEventRecord(evFork, 0);
    cudaStreamWaitEvent(s2, evFork, 0);

    extract_hist_kernel<<<(E + 255) / 256, 256, 0, s2>>>(ei, E);
    scanA_kernel<<<nb, SCAN_BS, 0, s2>>>(n);
    scanB_kernel<<<1, 128, 0, s2>>>(n, nb);
    scanC_kernel<<<nb, SCAN_BS, 0, s2>>>(n);
    scatter_kernel<<<(T + 255) / 256, 256, 0, s2>>>(E, T);
    cudaEventRecord(evJoin, s2);

    gemm_kernel<<<444, 256, gemm_smem>>>(x, W, Rw, Rb, att_s, att_d, n, ntiles);

    // join
    cudaStreamWaitEvent(0, evJoin, 0);
    aggregate_kernel<<<(n + 7) / 8, 256>>>(bias, lng, lnb, (float*)d_out, n);
}

// round 15
// speedup vs baseline: 2.1653x; 1.0808x over previous
#include <cuda_runtime.h>
#include <cuda_fp16.h>

#define NMAX 50000
#define EMAX 800000
#define HC   128
#define FIN  64
#define SCAN_BS 512
#define SCAN_NB ((NMAX + SCAN_BS - 1) / SCAN_BS)   // 98

// ---------------- scratch (static device arrays; no allocation) ----------------
__device__ __half h_h[NMAX * HC];       // x @ W  (fp16 gather path) [N,128]
__device__ float res_g[NMAX * HC];      // x @ res_w + res_b         [N,128]
__device__ float a_src_g[NMAX * 4];     // per-head src coeff        [N,4]
__device__ float a_dst_g[NMAX * 4];     // per-head dst coeff        [N,4]
__device__ int   deg_g[NMAX];           // zero at load; scanC re-zeros after use
__device__ int   rowptr_g[NMAX + 1];
__device__ int   rowcur_g[NMAX];
__device__ int   col_g[EMAX];
__device__ int   src_g[EMAX];
__device__ int   dst_g[EMAX];
__device__ int   bsum_g[SCAN_NB + 1];
__device__ int   boff_g[SCAN_NB + 1];

#define LEAKY(v) ((v) >= 0.f ? (v) : 0.2f * (v))

// ---------------- extract src/dst + histogram (detection folded in) -----------
__global__ void extract_hist_kernel(const void* __restrict__ raw, int E)
{
    __shared__ int s_has_nonzero_odd;
    const int* p32 = (const int*)raw;

    if (threadIdx.x == 0) s_has_nonzero_odd = 0;
    __syncthreads();
    int nwords = 1024;
    if (nwords > 2 * E) nwords = 2 * E;
    int nz = 0;
    for (int j = threadIdx.x; j < nwords / 2; j += blockDim.x)
        nz |= p32[2 * j + 1];
    if (nz) atomicOr(&s_has_nonzero_odd, 1);
    __syncthreads();
    int is64 = !s_has_nonzero_odd;

    int i = blockIdx.x * blockDim.x + threadIdx.x;
    if (i >= E) return;
    int s, d;
    if (is64) {
        const long long* p = (const long long*)raw;
        s = (int)p[i];
        d = (int)p[E + i];
    } else {
        s = p32[i];
        d = p32[E + i];
    }
    src_g[i] = s;
    dst_g[i] = d;
    atomicAdd(&deg_g[d], 1);
}

// ---------------- parallel 3-phase scan ----------------
__global__ void scanA_kernel(int n)
{
    __shared__ int sh[SCAN_BS];
    int t = threadIdx.x;
    int i = blockIdx.x * SCAN_BS + t;
    sh[t] = (i < n) ? deg_g[i] : 0;
    __syncthreads();
#pragma unroll
    for (int off = SCAN_BS / 2; off; off >>= 1) {
        if (t < off) sh[t] += sh[t + off];
        __syncthreads();
    }
    if (t == 0) bsum_g[blockIdx.x] = sh[0];
}

__global__ void scanB_kernel(int n, int nb)
{
    __shared__ int sh[128];
    int t = threadIdx.x;   // blockDim = 128 >= nb
    int v = (t < nb) ? bsum_g[t] : 0;
    sh[t] = v;
    __syncthreads();
#pragma unroll
    for (int off = 1; off < 128; off <<= 1) {
        int u = (t >= off) ? sh[t - off] : 0;
        __syncthreads();
        sh[t] += u;
        __syncthreads();
    }
    if (t < nb) boff_g[t] = sh[t] - v;        // exclusive
    if (t == nb - 1) rowptr_g[n] = sh[t];     // total
}

__global__ void scanC_kernel(int n)
{
    __shared__ int sh[SCAN_BS];
    int t = threadIdx.x;
    int i = blockIdx.x * SCAN_BS + t;
    int v = (i < n) ? deg_g[i] : 0;
    sh[t] = v;
    __syncthreads();
#pragma unroll
    for (int off = 1; off < SCAN_BS; off <<= 1) {
        int u = (t >= off) ? sh[t - off] : 0;
        __syncthreads();
        sh[t] += u;
        __syncthreads();
    }
    if (i < n) {
        int r = boff_g[blockIdx.x] + sh[t] - v;   // exclusive prefix
        rowptr_g[i] = r;
        rowcur_g[i] = r;
        deg_g[i] = 0;                              // ready for next launch
    }
}

// ---------------- scatter (2 edges/thread, guarded) ----------------
__global__ void scatter_kernel(int E, int T)
{
    int t = blockIdx.x * blockDim.x + threadIdx.x;
    if (t >= T) return;
    int i0 = t, i1 = t + T;
    int d0 = dst_g[i0], s0 = src_g[i0];
    int d1, s1;
    if (i1 < E) { d1 = dst_g[i1]; s1 = src_g[i1]; }
    int p0 = atomicAdd(&rowcur_g[d0], 1);
    int p1;
    if (i1 < E) p1 = atomicAdd(&rowcur_g[d1], 1);
    col_g[p0] = s0;
    if (i1 < E) col_g[p1] = s1;
}

// ---------------- tensor-core GEMM: h(fp16) = x@W ; res = x@res_w + b ; att ---
__device__ __forceinline__ void mma16816(float* c, const unsigned* a, const unsigned* b)
{
    asm volatile(
        "mma.sync.aligned.m16n8k16.row.col.f32.f16.f16.f32 "
        "{%0,%1,%2,%3}, {%4,%5,%6,%7}, {%8,%9}, {%0,%1,%2,%3};"
        : "+f"(c[0]), "+f"(c[1]), "+f"(c[2]), "+f"(c[3])
        : "r"(a[0]), "r"(a[1]), "r"(a[2]), "r"(a[3]), "r"(b[0]), "r"(b[1]));
}

#define W_WORDS (256 * 36)
#define X_WORDS (32 * 36)

__global__ void gemm_kernel(const float* __restrict__ x, const float* __restrict__ W,
                            const float* __restrict__ Rw, const float* __restrict__ Rb,
                            const float* __restrict__ att_s, const float* __restrict__ att_d,
                            int n, int ntiles)
{
    extern __shared__ unsigned smw[];
    unsigned* Wsh = smw;                       // fp16 n-major [col][k], stride 36 words
    unsigned* xsh = smw + W_WORDS;             // fp16 [node][k], stride 36 words
    float* asl = (float*)(smw + W_WORDS + X_WORDS);
    float* adl = asl + 128;
    float* rbs = adl + 128;

    int t = threadIdx.x;
    for (int idx = t; idx < FIN * 256; idx += 256) {
        int k = idx >> 8, c = idx & 255;
        float v = (c < 128) ? W[k * 128 + c] : Rw[k * 128 + (c - 128)];
        ((__half*)Wsh)[c * 72 + k] = __float2half(v);
    }
    if (t < 128) { asl[t] = att_s[t]; adl[t] = att_d[t]; rbs[t] = Rb[t]; }
    __syncthreads();

    int lane = t & 31, wid = t >> 5;
    int g = lane >> 2, qi = lane & 3;
    bool is_h = wid < 4;
    int colhalf = (wid & 3) * 32;

    for (int tile = blockIdx.x; tile < ntiles; tile += gridDim.x) {
        int nb = tile << 5;
        {
            int r = t >> 3, k0 = (t & 7) * 8;
            int node = nb + r;
            if (node >= n) node = n - 1;
            const float4* xr = (const float4*)(x + (size_t)node * FIN + k0);
            float4 v0 = xr[0], v1 = xr[1];
            __half2* dst = (__half2*)((__half*)xsh + r * 72 + k0);
            dst[0] = __floats2half2_rn(v0.x, v0.y);
            dst[1] = __floats2half2_rn(v0.z, v0.w);
            dst[2] = __floats2half2_rn(v1.x, v1.y);
            dst[3] = __floats2half2_rn(v1.z, v1.w);
        }
        __syncthreads();

        float acc[2][4][4];
#pragma unroll
        for (int nf = 0; nf < 2; nf++)
#pragma unroll
            for (int cf = 0; cf < 4; cf++)
#pragma unroll
                for (int q = 0; q < 4; q++) acc[nf][cf][q] = 0.f;

#pragma unroll
        for (int ks = 0; ks < 4; ks++) {
            int kw = ks * 8;
            unsigned a[2][4], b[4][2];
#pragma unroll
            for (int nf = 0; nf < 2; nf++) {
                unsigned base = (unsigned)(nf * 16 + g) * 36 + kw + qi;
                a[nf][0] = xsh[base];
                a[nf][1] = xsh[base + 8 * 36];
                a[nf][2] = xsh[base + 4];
                a[nf][3] = xsh[base + 4 + 8 * 36];
            }
#pragma unroll
            for (int cf = 0; cf < 4; cf++) {
                unsigned base = (unsigned)(wid * 32 + cf * 8 + g) * 36 + kw + qi;
                b[cf][0] = Wsh[base];
                b[cf][1] = Wsh[base + 4];
            }
#pragma unroll
            for (int nf = 0; nf < 2; nf++)
#pragma unroll
                for (int cf = 0; cf < 4; cf++)
                    mma16816(acc[nf][cf], a[nf], b[cf]);
        }
        __syncthreads();

#pragma unroll
        for (int nf = 0; nf < 2; nf++) {
            int node0 = nb + nf * 16 + g;
            int node1 = node0 + 8;
            float s0 = 0.f, d0 = 0.f, s1 = 0.f, d1 = 0.f;
#pragma unroll
            for (int cf = 0; cf < 4; cf++) {
                int c = colhalf + cf * 8 + qi * 2;
                if (is_h) {
                    // fp16 h store (4B per pair, aligned)
                    if (node0 < n)
                        *(__half2*)&h_h[(size_t)node0 * HC + c] =
                            __floats2half2_rn(acc[nf][cf][0], acc[nf][cf][1]);
                    if (node1 < n)
                        *(__half2*)&h_h[(size_t)node1 * HC + c] =
                            __floats2half2_rn(acc[nf][cf][2], acc[nf][cf][3]);
                    float as0 = asl[c], as1 = asl[c + 1];
                    float ad0 = adl[c], ad1 = adl[c + 1];
                    s0 += acc[nf][cf][0] * as0 + acc[nf][cf][1] * as1;
                    d0 += acc[nf][cf][0] * ad0 + acc[nf][cf][1] * ad1;
                    s1 += acc[nf][cf][2] * as0 + acc[nf][cf][3] * as1;
                    d1 += acc[nf][cf][2] * ad0 + acc[nf][cf][3] * ad1;
                } else {
                    float add0 = rbs[c], add1 = rbs[c + 1];
                    if (node0 < n) {
                        float2 v = make_float2(acc[nf][cf][0] + add0, acc[nf][cf][1] + add1);
                        *(float2*)&res_g[(size_t)node0 * HC + c] = v;
                    }
                    if (node1 < n) {
                        float2 v = make_float2(acc[nf][cf][2] + add0, acc[nf][cf][3] + add1);
                        *(float2*)&res_g[(size_t)node1 * HC + c] = v;
                    }
                }
            }
            if (is_h) {
#pragma unroll
                for (int off = 1; off < 4; off <<= 1) {
                    s0 += __shfl_xor_sync(0xffffffffu, s0, off);
                    d0 += __shfl_xor_sync(0xffffffffu, d0, off);
                    s1 += __shfl_xor_sync(0xffffffffu, s1, off);
                    d1 += __shfl_xor_sync(0xffffffffu, d1, off);
                }
                if (qi == 0) {
                    if (node0 < n) { a_src_g[node0 * 4 + wid] = s0; a_dst_g[node0 * 4 + wid] = d0; }
                    if (node1 < n) { a_src_g[node1 * 4 + wid] = s1; a_dst_g[node1 * 4 + wid] = d1; }
                }
            }
        }
    }
}

// ---------------- fused aggregate + softmax + ELU + residual + LayerNorm ------
// One warp per destination node. Lane l holds channels [4l,4l+4), head = l/8.
// h gathered fp16 (8B/lane/row = 256B/edge); all math fp32.
// Conversion via value-passed words + PTX cvt: NO address-of (round-9 lesson).
__device__ __forceinline__ void hadd(float4& acc, float w, unsigned lo, unsigned hi)
{
    float f0, f1, f2, f3;
    asm("{.reg .b16 a,b; mov.b32 {a,b}, %2; cvt.f32.f16 %0, a; cvt.f32.f16 %1, b;}"
        : "=f"(f0), "=f"(f1) : "r"(lo));
    asm("{.reg .b16 a,b; mov.b32 {a,b}, %2; cvt.f32.f16 %0, a; cvt.f32.f16 %1, b;}"
        : "=f"(f2), "=f"(f3) : "r"(hi));
    acc.x = fmaf(w, f0, acc.x);
    acc.y = fmaf(w, f1, acc.y);
    acc.z = fmaf(w, f2, acc.z);
    acc.w = fmaf(w, f3, acc.w);
}

__global__ void aggregate_kernel(const float* __restrict__ bias,
                                 const float* __restrict__ lng, const float* __restrict__ lnb,
                                 float* __restrict__ out, int n)
{
    int warp = (blockIdx.x * blockDim.x + threadIdx.x) >> 5;
    int lane = threadIdx.x & 31;
    if (warp >= n) return;
    int v = warp;
    int head = lane >> 3;

    float adh = a_dst_g[v * 4 + head];
    const uint2* hp = (const uint2*)h_h;

    // self loop
    float w0 = __expf(LEAKY(a_src_g[v * 4 + head] + adh));
    uint2 rv = hp[v * 32 + lane];
    float4 acc = make_float4(0.f, 0.f, 0.f, 0.f);
    hadd(acc, w0, rv.x, rv.y);
    float dsum = w0;

    int rs = rowptr_g[v], re = rowptr_g[v + 1];
    int i = rs;
    for (; i + 4 <= re; i += 4) {
        int u0 = col_g[i], u1 = col_g[i + 1], u2 = col_g[i + 2], u3 = col_g[i + 3];
        float e0 = a_src_g[u0 * 4 + head];
        float e1 = a_src_g[u1 * 4 + head];
        float e2 = a_src_g[u2 * 4 + head];
        float e3 = a_src_g[u3 * 4 + head];
        uint2 r0 = hp[u0 * 32 + lane];
        uint2 r1 = hp[u1 * 32 + lane];
        uint2 r2 = hp[u2 * 32 + lane];
        uint2 r3 = hp[u3 * 32 + lane];
        float x0 = __expf(LEAKY(e0 + adh));
        float x1 = __expf(LEAKY(e1 + adh));
        float x2 = __expf(LEAKY(e2 + adh));
        float x3 = __expf(LEAKY(e3 + adh));
        hadd(acc, x0, r0.x, r0.y);
        hadd(acc, x1, r1.x, r1.y);
        hadd(acc, x2, r2.x, r2.y);
        hadd(acc, x3, r3.x, r3.y);
        dsum += x0 + x1 + x2 + x3;
    }
    for (; i < re; i++) {
        int u = col_g[i];
        float wv = __expf(LEAKY(a_src_g[u * 4 + head] + adh));
        uint2 ru = hp[u * 32 + lane];
        hadd(acc, wv, ru.x, ru.y);
        dsum += wv;
    }

    float inv = 1.f / dsum;
    float4 b = ((const float4*)bias)[lane];
    float4 o;
    o.x = acc.x * inv + b.x;
    o.y = acc.y * inv + b.y;
    o.z = acc.z * inv + b.z;
    o.w = acc.w * inv + b.w;

    // ELU
    o.x = o.x > 0.f ? o.x : expm1f(o.x);
    o.y = o.y > 0.f ? o.y : expm1f(o.y);
    o.z = o.z > 0.f ? o.z : expm1f(o.z);
    o.w = o.w > 0.f ? o.w : expm1f(o.w);

    // residual
    float4 r = ((const float4*)res_g)[v * 32 + lane];
    o.x += r.x; o.y += r.y; o.z += r.z; o.w += r.w;

    // LayerNorm over 128 (warp-wide)
    float s = o.x + o.y + o.z + o.w;
#pragma unroll
    for (int off = 16; off; off >>= 1) s += __shfl_xor_sync(0xffffffffu, s, off);
    float mean = s * (1.f / 128.f);

    float cx = o.x - mean, cy = o.y - mean, cz = o.z - mean, cw = o.w - mean;
    float sq = cx * cx + cy * cy + cz * cz + cw * cw;
#pragma unroll
    for (int off = 16; off; off >>= 1) sq += __shfl_xor_sync(0xffffffffu, sq, off);
    float rinv = rsqrtf(sq * (1.f / 128.f) + 1e-5f);

    float4 g  = ((const float4*)lng)[lane];
    float4 lb = ((const float4*)lnb)[lane];
    float4 oo;
    oo.x = cx * rinv * g.x + lb.x;
    oo.y = cy * rinv * g.y + lb.y;
    oo.z = cz * rinv * g.z + lb.z;
    oo.w = cw * rinv * g.w + lb.w;

    ((float4*)out)[v * 32 + lane] = oo;
}

// ---------------- launch (fork-join: CSR build overlaps GEMM) ----------------
extern "C" void kernel_launch(void* const* d_in, const int* in_sizes, int n_in,
                              void* d_out, int out_size)
{
    const float* x     = (const float*)d_in[0];
    const void*  ei    = d_in[1];
    const float* W     = (const float*)d_in[2];
    const float* att_s = (const float*)d_in[3];
    const float* att_d = (const float*)d_in[4];
    const float* bias  = (const float*)d_in[5];
    const float* Rw    = (const float*)d_in[6];
    const float* Rb    = (const float*)d_in[7];
    const float* lng   = (const float*)d_in[8];
    const float* lnb   = (const float*)d_in[9];

    int n = in_sizes[0] / FIN;
    int E = in_sizes[1] / 2;
    int ntiles = (n + 31) / 32;
    int nb = (n + SCAN_BS - 1) / SCAN_BS;
    int T = (E + 1) / 2;

    static cudaStream_t s2 = 0;
    static cudaEvent_t evFork = 0, evJoin = 0;
    static int inited = 0;
    int gemm_smem = (W_WORDS + X_WORDS + 384) * (int)sizeof(unsigned);  // ~43KB
    if (!inited) {
        cudaFuncSetAttribute(gemm_kernel, cudaFuncAttributeMaxDynamicSharedMemorySize, gemm_smem);
        cudaStreamCreateWithFlags(&s2, cudaStreamNonBlocking);
        cudaEventCreateWithFlags(&evFork, cudaEventDisableTiming);
        cudaEventCreateWithFlags(&evJoin, cudaEventDisableTiming);
        inited = 1;
    }

    // fork: s2 does the CSR build while stream 0 does the GEMM
    cudaEventRecord(evFork, 0);
    cudaStreamWaitEvent(s2, evFork, 0);

    extract_hist_kernel<<<(E + 255) / 256, 256, 0, s2>>>(ei, E);
    scanA_kernel<<<nb, SCAN_BS, 0, s2>>>(n);
    scanB_kernel<<<1, 128, 0, s2>>>(n, nb);
    scanC_kernel<<<nb, SCAN_BS, 0, s2>>>(n);
    scatter_kernel<<<(T + 255) / 256, 256, 0, s2>>>(E, T);
    cudaEventRecord(evJoin, s2);

    gemm_kernel<<<444, 256, gemm_smem>>>(x, W, Rw, Rb, att_s, att_d, n, ntiles);

    // join
    cudaStreamWaitEvent(0, evJoin, 0);
    aggregate_kernel<<<(n + 7) / 8, 256>>>(bias, lng, lnb, (float*)d_out, n);
}